// round 10
// baseline (speedup 1.0000x reference)
#include <cuda_runtime.h>
#include <cuda_bf16.h>
#include <cstddef>

// Problem constants (fixed by the reference setup)
#define BB      16
#define TRED    512
#define CC      512
#define C4      (CC / 4)   // float4 per row = 128
#define TT2     64         // t-rows per gather block
#define NTH     512        // threads per block
#define MAXLEN  8192       // total = sum(dur) <= TRED * MAX_DUR(16) = 8192

// Scratch: per-(b,t) segment index, -1 = invalid (write zeros).
// __device__ global (no allocation allowed in kernel_launch).
__device__ int g_seg[BB * MAXLEN];

// ---------------------------------------------------------------------------
// Kernel 1: one block per batch. Scan durations once, searchsorted for every
// t, fill g_seg + mask. Tiny (16 blocks), runs in ~2us.
// ---------------------------------------------------------------------------
__global__ __launch_bounds__(NTH)
void seg_kernel(const int* __restrict__ dur,
                const int* __restrict__ target_T,
                float*     __restrict__ out,
                int max_len, int write_mask)
{
    __shared__ int csum[TRED];

    const int b   = blockIdx.x;
    const int tid = threadIdx.x;

    // inclusive prefix scan of durations[b] (Hillis-Steele, 512 lanes)
    csum[tid] = dur[b * TRED + tid];
    __syncthreads();
    #pragma unroll
    for (int off = 1; off < TRED; off <<= 1) {
        int add = (tid >= off) ? csum[tid - off] : 0;
        __syncthreads();
        csum[tid] += add;
        __syncthreads();
    }

    const int total    = csum[TRED - 1];
    const int curr_len = min(total, target_T[b]);   // == total by construction

    float* mask = out + (size_t)BB * max_len * CC;

    for (int t = tid; t < max_len; t += NTH) {
        const int valid = (t < curr_len);
        int seg = -1;
        if (valid) {
            // first i with csum[i] > t  (searchsorted right)
            int lo = 0, hi = TRED;
            while (lo < hi) {
                int mid = (lo + hi) >> 1;
                if (csum[mid] > t) hi = mid; else lo = mid + 1;
            }
            seg = min(lo, TRED - 1);
        }
        g_seg[b * MAXLEN + t] = seg;
        if (write_mask) mask[(size_t)b * max_len + t] = valid ? 0.0f : 1.0f;
    }
}

// ---------------------------------------------------------------------------
// Kernel 2: pure streamed gather. Each block handles TT2=64 t-rows of one
// batch: load 64 precomputed seg indices into smem, then float4 gather/store.
// No scan, no search — keep the SMs issuing memory ops.
// ---------------------------------------------------------------------------
__global__ __launch_bounds__(NTH)
void gather_kernel(const float* __restrict__ px,
                   float*       __restrict__ out,
                   int max_len)
{
    __shared__ int seg_s[TT2];

    const int b   = blockIdx.y;
    const int tid = threadIdx.x;
    const int t0  = blockIdx.x * TT2;

    if (tid < TT2) {
        const int t = t0 + tid;
        seg_s[tid] = (t < max_len) ? g_seg[b * MAXLEN + t] : -1;
    }
    __syncthreads();

    const int row = tid >> 7;      // 0..3 (128 threads per t-row)
    const int c4  = tid & (C4 - 1);
    const float4* px4  = (const float4*)px;
    float4*       out4 = (float4*)out;

    #pragma unroll
    for (int r = row; r < TT2; r += NTH / C4) {
        const int t = t0 + r;
        if (t >= max_len) continue;
        const int s = seg_s[r];
        float4 v;
        if (s >= 0) {
            v = px4[((size_t)b * TRED + s) * C4 + c4];
        } else {
            v = make_float4(0.0f, 0.0f, 0.0f, 0.0f);
        }
        out4[((size_t)b * max_len + t) * C4 + c4] = v;
    }
}

extern "C" void kernel_launch(void* const* d_in, const int* in_sizes, int n_in,
                              void* d_out, int out_size)
{
    const float* px  = (const float*)d_in[0];   // pooled_x  (B, T_RED, C) f32
    const int*   dur = (const int*)  d_in[1];   // durations (B, T_RED)   i32
    const int*   tgt = (const int*)  d_in[2];   // target_T  (B,)         i32

    // Recover max_len from out_size. Layout: [x (B*max_len*C)] ++ [mask (B*max_len)].
    int max_len, write_mask;
    if (out_size % (BB * (CC + 1)) == 0) {
        max_len    = out_size / (BB * (CC + 1));
        write_mask = 1;
    } else {
        max_len    = out_size / (BB * CC);   // fallback: x-only output
        write_mask = 0;
    }

    seg_kernel<<<BB, NTH>>>(dur, tgt, (float*)d_out, max_len, write_mask);

    dim3 grid((max_len + TT2 - 1) / TT2, BB);
    gather_kernel<<<grid, NTH>>>(px, (float*)d_out, max_len);
}

// round 11
// speedup vs baseline: 1.0188x; 1.0188x over previous
#include <cuda_runtime.h>
#include <cuda_bf16.h>
#include <cstddef>

// Problem constants (fixed by the reference setup)
#define BB      16
#define TRED    512
#define CC      512
#define C4      (CC / 4)   // float4 per row = 128
#define TT2     64         // t-rows per gather block
#define NTH     512        // threads per block
#define MAXLEN  8192       // total = sum(dur) <= TRED * MAX_DUR(16) = 8192

// Scratch: per-(b,t) segment index, -1 = invalid (write zeros).
// __device__ global (no allocation allowed in kernel_launch).
__device__ int g_seg[BB * MAXLEN];

// ---------------------------------------------------------------------------
// Kernel 1: one block per batch. Scan durations once, searchsorted for every
// t, fill g_seg + mask. Tiny (16 blocks), runs in ~2us.
// ---------------------------------------------------------------------------
__global__ __launch_bounds__(NTH)
void seg_kernel(const int* __restrict__ dur,
                const int* __restrict__ target_T,
                float*     __restrict__ out,
                int max_len, int write_mask)
{
    __shared__ int csum[TRED];

    const int b   = blockIdx.x;
    const int tid = threadIdx.x;

    // inclusive prefix scan of durations[b] (Hillis-Steele, 512 lanes)
    csum[tid] = dur[b * TRED + tid];
    __syncthreads();
    #pragma unroll
    for (int off = 1; off < TRED; off <<= 1) {
        int add = (tid >= off) ? csum[tid - off] : 0;
        __syncthreads();
        csum[tid] += add;
        __syncthreads();
    }

    const int total    = csum[TRED - 1];
    const int curr_len = min(total, target_T[b]);   // == total by construction

    float* mask = out + (size_t)BB * max_len * CC;

    for (int t = tid; t < max_len; t += NTH) {
        const int valid = (t < curr_len);
        int seg = -1;
        if (valid) {
            // first i with csum[i] > t  (searchsorted right)
            int lo = 0, hi = TRED;
            while (lo < hi) {
                int mid = (lo + hi) >> 1;
                if (csum[mid] > t) hi = mid; else lo = mid + 1;
            }
            seg = min(lo, TRED - 1);
        }
        g_seg[b * MAXLEN + t] = seg;
        if (write_mask) mask[(size_t)b * max_len + t] = valid ? 0.0f : 1.0f;
    }
}

// ---------------------------------------------------------------------------
// Kernel 2: pure streamed gather. Each block handles TT2=64 t-rows of one
// batch: load 64 precomputed seg indices into smem, then float4 gather/store.
// No scan, no search — keep the SMs issuing memory ops.
// ---------------------------------------------------------------------------
__global__ __launch_bounds__(NTH)
void gather_kernel(const float* __restrict__ px,
                   float*       __restrict__ out,
                   int max_len)
{
    __shared__ int seg_s[TT2];

    const int b   = blockIdx.y;
    const int tid = threadIdx.x;
    const int t0  = blockIdx.x * TT2;

    if (tid < TT2) {
        const int t = t0 + tid;
        seg_s[tid] = (t < max_len) ? g_seg[b * MAXLEN + t] : -1;
    }
    __syncthreads();

    const int row = tid >> 7;      // 0..3 (128 threads per t-row)
    const int c4  = tid & (C4 - 1);
    const float4* px4  = (const float4*)px;
    float4*       out4 = (float4*)out;

    #pragma unroll
    for (int r = row; r < TT2; r += NTH / C4) {
        const int t = t0 + r;
        if (t >= max_len) continue;
        const int s = seg_s[r];
        float4 v;
        if (s >= 0) {
            v = px4[((size_t)b * TRED + s) * C4 + c4];
        } else {
            v = make_float4(0.0f, 0.0f, 0.0f, 0.0f);
        }
        out4[((size_t)b * max_len + t) * C4 + c4] = v;
    }
}

extern "C" void kernel_launch(void* const* d_in, const int* in_sizes, int n_in,
                              void* d_out, int out_size)
{
    const float* px  = (const float*)d_in[0];   // pooled_x  (B, T_RED, C) f32
    const int*   dur = (const int*)  d_in[1];   // durations (B, T_RED)   i32
    const int*   tgt = (const int*)  d_in[2];   // target_T  (B,)         i32

    // Recover max_len from out_size. Layout: [x (B*max_len*C)] ++ [mask (B*max_len)].
    int max_len, write_mask;
    if (out_size % (BB * (CC + 1)) == 0) {
        max_len    = out_size / (BB * (CC + 1));
        write_mask = 1;
    } else {
        max_len    = out_size / (BB * CC);   // fallback: x-only output
        write_mask = 0;
    }

    seg_kernel<<<BB, NTH>>>(dur, tgt, (float*)d_out, max_len, write_mask);

    dim3 grid((max_len + TT2 - 1) / TT2, BB);
    gather_kernel<<<grid, NTH>>>(px, (float*)d_out, max_len);
}

// round 12
// speedup vs baseline: 1.4286x; 1.4022x over previous
#include <cuda_runtime.h>
#include <cuda_bf16.h>
#include <cstddef>

// Problem constants (fixed by the reference setup)
#define BB      16
#define TRED    512
#define CC      512
#define C4      (CC / 4)   // float4 per row = 128
#define TT      64         // t-rows per block
#define NTH     512        // threads per block
#define NWARP   (NTH / 32) // 16

// One fused kernel.
//   head (cheap): 512-wide inclusive scan of durations[b] via warp shfl scans
//                 (3 __syncthreads total), binary search seg for TT rows, mask.
//   body (hot)  : float4 streamed gather px[b,seg,:] -> out[b,t,:], __stcs
//                 evict-first stores so the 137MB write stream doesn't evict
//                 the 16.8MB gather source from L2.
__global__ __launch_bounds__(NTH)
void upsample_fused(const float* __restrict__ px,
                    const int*   __restrict__ dur,
                    const int*   __restrict__ target_T,
                    float*       __restrict__ out,
                    int max_len, int write_mask)
{
    __shared__ int csum[TRED];
    __shared__ int wsum[NWARP];
    __shared__ int seg_s[TT];

    const int b    = blockIdx.y;
    const int tid  = threadIdx.x;
    const int lane = tid & 31;
    const int wid  = tid >> 5;
    const int t0   = blockIdx.x * TT;

    // ---- inclusive scan of durations[b] (warp shfl scan, 3 syncs) ----
    int x = dur[b * TRED + tid];
    #pragma unroll
    for (int off = 1; off < 32; off <<= 1) {
        int y = __shfl_up_sync(0xffffffffu, x, off);
        if (lane >= off) x += y;
    }
    if (lane == 31) wsum[wid] = x;
    __syncthreads();
    if (wid == 0) {
        int w = (lane < NWARP) ? wsum[lane] : 0;
        #pragma unroll
        for (int off = 1; off < NWARP; off <<= 1) {
            int y = __shfl_up_sync(0xffffffffu, w, off);
            if (lane >= off) w += y;
        }
        if (lane < NWARP) wsum[lane] = w;
    }
    __syncthreads();
    csum[tid] = x + ((wid > 0) ? wsum[wid - 1] : 0);
    __syncthreads();

    const int total    = csum[TRED - 1];
    const int curr_len = min(total, target_T[b]);   // == total by construction

    // ---- first TT threads: searchsorted + mask write ----
    if (tid < TT) {
        const int t     = t0 + tid;
        const int valid = (t < max_len) && (t < curr_len);
        int seg = -1;
        if (valid) {
            int lo = 0, hi = TRED;                   // first i with csum[i] > t
            while (lo < hi) {
                int mid = (lo + hi) >> 1;
                if (csum[mid] > t) hi = mid; else lo = mid + 1;
            }
            seg = min(lo, TRED - 1);
        }
        seg_s[tid] = seg;
        if (write_mask && t < max_len) {
            float* mask = out + (size_t)BB * max_len * CC;
            __stcs(&mask[(size_t)b * max_len + t], valid ? 0.0f : 1.0f);
        }
    }
    __syncthreads();

    // ---- hot loop: 128 threads per t-row, 4 rows per wave, 16 waves ----
    const int row = tid >> 7;        // 0..3
    const int c4  = tid & (C4 - 1);  // 0..127
    const float4* px4  = (const float4*)px;
    float4*       out4 = (float4*)out;

    #pragma unroll
    for (int r = row; r < TT; r += NTH / C4) {
        const int t = t0 + r;
        if (t >= max_len) continue;
        const int s = seg_s[r];
        float4 v;
        if (s >= 0) {
            v = __ldg(&px4[((size_t)b * TRED + s) * C4 + c4]);
        } else {
            v = make_float4(0.0f, 0.0f, 0.0f, 0.0f);
        }
        __stcs(&out4[((size_t)b * max_len + t) * C4 + c4], v);
    }
}

extern "C" void kernel_launch(void* const* d_in, const int* in_sizes, int n_in,
                              void* d_out, int out_size)
{
    const float* px  = (const float*)d_in[0];   // pooled_x  (B, T_RED, C) f32
    const int*   dur = (const int*)  d_in[1];   // durations (B, T_RED)   i32
    const int*   tgt = (const int*)  d_in[2];   // target_T  (B,)         i32

    // Recover max_len from out_size. Layout: [x (B*max_len*C)] ++ [mask (B*max_len)].
    int max_len, write_mask;
    if (out_size % (BB * (CC + 1)) == 0) {
        max_len    = out_size / (BB * (CC + 1));
        write_mask = 1;
    } else {
        max_len    = out_size / (BB * CC);   // fallback: x-only output
        write_mask = 0;
    }

    dim3 grid((max_len + TT - 1) / TT, BB);
    upsample_fused<<<grid, NTH>>>(px, dur, tgt, (float*)d_out, max_len, write_mask);
}